// round 1
// baseline (speedup 1.0000x reference)
#include <cuda_runtime.h>

// Problem constants (fixed shapes from reference)
#define CIN   256
#define COUT  256
#define HDIM  64
#define WDIM  64
#define BATCH 4
#define K2    9
#define HW    (HDIM * WDIM)        // 4096
#define M_GEMM (K2 * COUT)         // 2304
#define K_GEMM CIN                 // 256

// Scratch: blended weights [m = k*COUT + o][c], and G[b][m][pos]
__device__ float g_W[M_GEMM * K_GEMM];             // 2.36 MB
__device__ float g_G[BATCH * M_GEMM * HW];         // 151 MB

// ---------------------------------------------------------------------------
// Kernel 1: circle-blend the 3x3 weights, store as GEMM A matrix [m][c]
// ---------------------------------------------------------------------------
__global__ void blend_weights_kernel(const float* __restrict__ weight) {
    int t = blockIdx.x * blockDim.x + threadIdx.x;
    if (t >= COUT * CIN) return;
    int o = t >> 8;        // 0..255
    int c = t & 255;       // 0..255
    const float* wp = weight + ((size_t)(o * CIN + c)) * K2;
    float w0 = wp[0], w1 = wp[1], w2 = wp[2];
    float w3 = wp[3], w4 = wp[4], w5 = wp[5];
    float w6 = wp[6], w7 = wp[7], w8 = wp[8];

    const float A  = 0.7071067811865476f;
    const float Bc = 1.0f - 0.7071067811865476f;

    float t01 = A * w0 + Bc * w1;   // A*w0 + B*w1
    float t34 = A * w3 + Bc * w4;   // A*w3 + B*w4
    float t12 = Bc * w1 + A * w2;   // B*w1 + A*w2
    float t45 = Bc * w4 + A * w5;   // B*w4 + A*w5
    float t67 = A * w6 + Bc * w7;   // A*w6 + B*w7
    float t78 = Bc * w7 + A * w8;   // B*w7 + A*w8

    float nw0 = A * t01 + Bc * t34;
    float nw2 = A * t12 + Bc * t45;
    float nw6 = Bc * t34 + A * t67;
    float nw8 = Bc * t45 + A * t78;

    float nw[K2] = { nw0, w1, nw2, w3, w4, w5, nw6, w7, nw8 };
#pragma unroll
    for (int k = 0; k < K2; k++) {
        g_W[(k * COUT + o) * K_GEMM + c] = nw[k];
    }
}

// ---------------------------------------------------------------------------
// Kernel 2: SGEMM  G[b][m][n] = sum_c g_W[m][c] * x[b][c][n]
//   M=2304, K=256, N=4096 per batch.  128x128 tile, BK=8, 8x8 per thread.
// ---------------------------------------------------------------------------
__global__ __launch_bounds__(256) void gemm_kernel(const float* __restrict__ X) {
    __shared__ float As[8][128];
    __shared__ float Bs[8][128];

    const int b  = blockIdx.z;
    const float* Bmat = X + (size_t)b * CIN * HW;
    float* Gout = g_G + (size_t)b * M_GEMM * HW;

    const int m0 = blockIdx.y * 128;
    const int n0 = blockIdx.x * 128;
    const int tid = threadIdx.x;

    const int arow = tid >> 1;            // 0..127
    const int acol = (tid & 1) * 4;       // 0 or 4
    const int brow = tid >> 5;            // 0..7
    const int bcol = (tid & 31) * 4;      // 0..124
    const int trow = (tid >> 4) * 8;      // 0..120
    const int tcol = (tid & 15) * 8;      // 0..120

    float acc[8][8] = {};
    float ar[8], br[8];

    for (int k0 = 0; k0 < K_GEMM; k0 += 8) {
        float4 a4 = *reinterpret_cast<const float4*>(
            g_W + (m0 + arow) * K_GEMM + k0 + acol);
        As[acol + 0][arow] = a4.x;
        As[acol + 1][arow] = a4.y;
        As[acol + 2][arow] = a4.z;
        As[acol + 3][arow] = a4.w;

        *reinterpret_cast<float4*>(&Bs[brow][bcol]) =
            *reinterpret_cast<const float4*>(Bmat + (k0 + brow) * HW + n0 + bcol);

        __syncthreads();

#pragma unroll
        for (int kk = 0; kk < 8; kk++) {
#pragma unroll
            for (int i = 0; i < 8; i++) ar[i] = As[kk][trow + i];
#pragma unroll
            for (int j = 0; j < 8; j++) br[j] = Bs[kk][tcol + j];
#pragma unroll
            for (int i = 0; i < 8; i++)
#pragma unroll
                for (int j = 0; j < 8; j++)
                    acc[i][j] += ar[i] * br[j];
        }
        __syncthreads();
    }

#pragma unroll
    for (int i = 0; i < 8; i++) {
        float4* dst = reinterpret_cast<float4*>(
            Gout + (size_t)(m0 + trow + i) * HW + n0 + tcol);
        dst[0] = make_float4(acc[i][0], acc[i][1], acc[i][2], acc[i][3]);
        dst[1] = make_float4(acc[i][4], acc[i][5], acc[i][6], acc[i][7]);
    }
}

// ---------------------------------------------------------------------------
// Kernel 3: combine — bilinear gather of G with per-corner coeffs * mask
//   out[b,o,p] = bias[o] + sum_k sum_corner cw * G[b,k,o,idx]
//   128 pixels per CTA; thread = pixel; loop o in groups of 4.
// ---------------------------------------------------------------------------
#define TP 128
__global__ __launch_bounds__(TP) void combine_kernel(
    const float* __restrict__ offset,
    const float* __restrict__ mask,
    const float* __restrict__ bias,
    float* __restrict__ out)
{
    __shared__ int4   s_idx[TP * K2];
    __shared__ float4 s_cw[TP * K2];
    __shared__ float  s_bias[COUT];

    const int b   = blockIdx.y;
    const int p0  = blockIdx.x * TP;
    const int tid = threadIdx.x;

    for (int i = tid; i < COUT; i += TP) s_bias[i] = bias[i];

    // Phase 1: per (pixel, tap) corner indices and coefficients
    for (int e = tid; e < TP * K2; e += TP) {
        int lp = e / K2;
        int k  = e - lp * K2;
        int p  = p0 + lp;
        int py = p >> 6;
        int px = p & 63;

        float dy = offset[((b * 2 * K2) + 2 * k    ) * HW + p];
        float dx = offset[((b * 2 * K2) + 2 * k + 1) * HW + p];
        float m  = mask[(b * K2 + k) * HW + p];

        float yy = (float)(py - 1 + (k / 3)) + dy;
        float xx = (float)(px - 1 + (k % 3)) + dx;

        float y0f = floorf(yy), x0f = floorf(xx);
        float ly = yy - y0f, lx = xx - x0f;
        float hy = 1.0f - ly, hx = 1.0f - lx;
        int y0 = (int)y0f, x0 = (int)x0f;
        int y1 = y0 + 1,   x1 = x0 + 1;

        bool vy0 = (y0 >= 0) && (y0 < HDIM);
        bool vy1 = (y1 >= 0) && (y1 < HDIM);
        bool vx0 = (x0 >= 0) && (x0 < WDIM);
        bool vx1 = (x1 >= 0) && (x1 < WDIM);

        int cy0 = min(max(y0, 0), HDIM - 1);
        int cy1 = min(max(y1, 0), HDIM - 1);
        int cx0 = min(max(x0, 0), WDIM - 1);
        int cx1 = min(max(x1, 0), WDIM - 1);

        s_idx[e] = make_int4(cy0 * WDIM + cx0, cy0 * WDIM + cx1,
                             cy1 * WDIM + cx0, cy1 * WDIM + cx1);
        s_cw[e]  = make_float4((vy0 && vx0) ? hy * hx * m : 0.0f,
                               (vy0 && vx1) ? hy * lx * m : 0.0f,
                               (vy1 && vx0) ? ly * hx * m : 0.0f,
                               (vy1 && vx1) ? ly * lx * m : 0.0f);
    }
    __syncthreads();

    // Phase 2: accumulate over taps/corners for 4 output channels at a time
    const int p = p0 + tid;
    for (int o = 0; o < COUT; o += 4) {
        float a0 = s_bias[o + 0];
        float a1 = s_bias[o + 1];
        float a2 = s_bias[o + 2];
        float a3 = s_bias[o + 3];
#pragma unroll
        for (int k = 0; k < K2; k++) {
            int4   id = s_idx[tid * K2 + k];
            float4 cw = s_cw[tid * K2 + k];
            const float* Gb = g_G + ((size_t)((b * K2 + k) * COUT + o)) * HW;
            const float* G0 = Gb;
            const float* G1 = Gb + HW;
            const float* G2 = Gb + 2 * HW;
            const float* G3 = Gb + 3 * HW;
            a0 += cw.x * G0[id.x] + cw.y * G0[id.y] + cw.z * G0[id.z] + cw.w * G0[id.w];
            a1 += cw.x * G1[id.x] + cw.y * G1[id.y] + cw.z * G1[id.z] + cw.w * G1[id.w];
            a2 += cw.x * G2[id.x] + cw.y * G2[id.y] + cw.z * G2[id.z] + cw.w * G2[id.w];
            a3 += cw.x * G3[id.x] + cw.y * G3[id.y] + cw.z * G3[id.z] + cw.w * G3[id.w];
        }
        out[((size_t)(b * COUT + o + 0)) * HW + p] = a0;
        out[((size_t)(b * COUT + o + 1)) * HW + p] = a1;
        out[((size_t)(b * COUT + o + 2)) * HW + p] = a2;
        out[((size_t)(b * COUT + o + 3)) * HW + p] = a3;
    }
}

// ---------------------------------------------------------------------------
extern "C" void kernel_launch(void* const* d_in, const int* in_sizes, int n_in,
                              void* d_out, int out_size) {
    const float* x      = (const float*)d_in[0];   // [4,256,64,64]
    const float* offset = (const float*)d_in[1];   // [4,18,64,64]
    const float* mask   = (const float*)d_in[2];   // [4,9,64,64]
    const float* weight = (const float*)d_in[3];   // [256,256,3,3]
    const float* bias   = (const float*)d_in[4];   // [256]
    float* out = (float*)d_out;                    // [4,256,64,64]

    blend_weights_kernel<<<(COUT * CIN + 255) / 256, 256>>>(weight);
    gemm_kernel<<<dim3(HW / 128, M_GEMM / 128, BATCH), 256>>>(x);
    combine_kernel<<<dim3(HW / TP, BATCH), TP>>>(offset, mask, bias, out);
}

// round 3
// speedup vs baseline: 1.8514x; 1.8514x over previous
#include <cuda_runtime.h>
#include <cuda_bf16.h>
#include <cstdint>

// ---------------- problem constants ----------------
#define CIN    256
#define COUT   256
#define HDIM   64
#define WDIM   64
#define BATCH  4
#define K2     9
#define HW     4096
#define M_GEMM 2304          // K2 * COUT
#define K_GEMM 256           // CIN

// ---------------- GEMM tiling ----------------
#define BM 128
#define BN 128
#define BK 64                          // bf16 elements per chunk (128B rows)
#define NCHUNK (K_GEMM / BK)           // 4
#define TILE_B (BM * BK * 2)           // 16384 bytes per operand tile
#define STAGE_B (4 * TILE_B)           // Ahi, Alo, Bhi, Blo = 64 KB
#define SMEM_DYN (2 * STAGE_B)         // 128 KB

// ---------------- scratch (device globals) ----------------
__device__ __nv_bfloat16 g_Whi[M_GEMM * K_GEMM];     // [m][c]
__device__ __nv_bfloat16 g_Wlo[M_GEMM * K_GEMM];
__device__ __nv_bfloat16 g_Xhi[BATCH * HW * CIN];    // [b][n][c]
__device__ __nv_bfloat16 g_Xlo[BATCH * HW * CIN];
__device__ float g_G[(size_t)BATCH * M_GEMM * HW];   // [b][m][n]  151 MB

// ---------------- PTX helpers ----------------
__device__ __forceinline__ uint32_t smem_u32(const void* p) {
    uint32_t a;
    asm("{ .reg .u64 t; cvta.to.shared.u64 t, %1; cvt.u32.u64 %0, t; }" : "=r"(a) : "l"(p));
    return a;
}
#define CP16(dst, src)  asm volatile("cp.async.cg.shared.global [%0], [%1], 16;" :: "r"(dst), "l"(src) : "memory")
#define CP_COMMIT()     asm volatile("cp.async.commit_group;" ::: "memory")
#define CP_WAIT(n)      asm volatile("cp.async.wait_group %0;" :: "n"(n) : "memory")

__device__ __forceinline__ void ldsm_x4(uint32_t* r, uint32_t addr) {
    asm volatile("ldmatrix.sync.aligned.m8n8.x4.shared.b16 {%0,%1,%2,%3}, [%4];"
                 : "=r"(r[0]), "=r"(r[1]), "=r"(r[2]), "=r"(r[3]) : "r"(addr));
}
__device__ __forceinline__ void mma_bf16(float* d, const uint32_t* a, const uint32_t* b) {
    asm volatile("mma.sync.aligned.m16n8k16.row.col.f32.bf16.bf16.f32 "
                 "{%0,%1,%2,%3}, {%4,%5,%6,%7}, {%8,%9}, {%0,%1,%2,%3};"
                 : "+f"(d[0]), "+f"(d[1]), "+f"(d[2]), "+f"(d[3])
                 : "r"(a[0]), "r"(a[1]), "r"(a[2]), "r"(a[3]), "r"(b[0]), "r"(b[1]));
}
__device__ __forceinline__ uint32_t swz(uint32_t off) { return off ^ ((off >> 3) & 0x70); }

// ---------------------------------------------------------------------------
// Kernel 1: circle-blend weights, split into bf16 hi/lo, store K-major [m][c]
// ---------------------------------------------------------------------------
__global__ void blend_weights_kernel(const float* __restrict__ weight) {
    int t = blockIdx.x * blockDim.x + threadIdx.x;
    if (t >= COUT * CIN) return;
    int o = t >> 8;
    int c = t & 255;
    const float* wp = weight + ((size_t)(o * CIN + c)) * K2;
    float w0 = wp[0], w1 = wp[1], w2 = wp[2];
    float w3 = wp[3], w4 = wp[4], w5 = wp[5];
    float w6 = wp[6], w7 = wp[7], w8 = wp[8];

    const float A  = 0.7071067811865476f;
    const float Bc = 1.0f - 0.7071067811865476f;

    float t01 = A * w0 + Bc * w1;
    float t34 = A * w3 + Bc * w4;
    float t12 = Bc * w1 + A * w2;
    float t45 = Bc * w4 + A * w5;
    float t67 = A * w6 + Bc * w7;
    float t78 = Bc * w7 + A * w8;

    float nw[K2];
    nw[0] = A * t01 + Bc * t34;  nw[1] = w1;
    nw[2] = A * t12 + Bc * t45;  nw[3] = w3;  nw[4] = w4;  nw[5] = w5;
    nw[6] = Bc * t34 + A * t67;  nw[7] = w7;
    nw[8] = Bc * t45 + A * t78;

#pragma unroll
    for (int k = 0; k < K2; k++) {
        float v = nw[k];
        __nv_bfloat16 hi = __float2bfloat16_rn(v);
        float lo = v - __bfloat162float(hi);
        size_t idx = (size_t)(k * COUT + o) * K_GEMM + c;
        g_Whi[idx] = hi;
        g_Wlo[idx] = __float2bfloat16_rn(lo);
    }
}

// ---------------------------------------------------------------------------
// Kernel 2: transpose x[b][c][n] -> Xt[b][n][c], split bf16 hi/lo
// ---------------------------------------------------------------------------
__global__ __launch_bounds__(256) void transpose_split_kernel(const float* __restrict__ X) {
    __shared__ float t[32][33];
    int b  = blockIdx.z;
    int n0 = blockIdx.x * 32;
    int c0 = blockIdx.y * 32;
    int tx = threadIdx.x, ty = threadIdx.y;

    const float* src = X + ((size_t)b * CIN + c0) * HW + n0;
#pragma unroll
    for (int i = ty; i < 32; i += 8)
        t[i][tx] = src[(size_t)i * HW + tx];
    __syncthreads();

    __nv_bfloat16* dhi = g_Xhi + ((size_t)b * HW + n0) * CIN + c0;
    __nv_bfloat16* dlo = g_Xlo + ((size_t)b * HW + n0) * CIN + c0;
#pragma unroll
    for (int i = ty; i < 32; i += 8) {
        float v = t[tx][i];
        __nv_bfloat16 hi = __float2bfloat16_rn(v);
        float lo = v - __bfloat162float(hi);
        dhi[(size_t)i * CIN + tx] = hi;
        dlo[(size_t)i * CIN + tx] = __float2bfloat16_rn(lo);
    }
}

// ---------------------------------------------------------------------------
// Kernel 3: bf16x2 split GEMM via mma.sync  G[b][m][n] = sum_c W[m][c]*Xt[b][n][c]
// ---------------------------------------------------------------------------
extern __shared__ __align__(1024) unsigned char dsmem[];

__global__ __launch_bounds__(256, 1) void gemm_bf16_kernel() {
    const int tid  = threadIdx.x;
    const int wid  = tid >> 5;
    const int lane = tid & 31;
    const int warp_m = wid >> 2;       // 0..1  (64 rows each)
    const int warp_n = wid & 3;        // 0..3  (32 cols each)

    const int b  = blockIdx.z;
    const int m0 = blockIdx.y * BM;
    const int n0 = blockIdx.x * BN;

    const uint32_t sbase = smem_u32(dsmem);

    const __nv_bfloat16* Ahi_g = g_Whi + (size_t)m0 * K_GEMM;
    const __nv_bfloat16* Alo_g = g_Wlo + (size_t)m0 * K_GEMM;
    const __nv_bfloat16* Bhi_g = g_Xhi + ((size_t)b * HW + n0) * CIN;
    const __nv_bfloat16* Blo_g = g_Xlo + ((size_t)b * HW + n0) * CIN;

    // ---- cp.async one K-chunk into stage (ch & 1) ----
    auto copy_chunk = [&](int ch) {
        const uint32_t sb = sbase + (ch & 1) * STAGE_B;
        const int k0 = ch * BK;
#pragma unroll
        for (int t = 0; t < 4; t++) {
            int u = t * 256 + tid;          // 0..1023
            int r = u >> 3;                 // row 0..127
            int q = u & 7;                  // 16B unit in row
            uint32_t doff = swz((uint32_t)(r * 128 + q * 16));
            const __nv_bfloat16* sa_h = Ahi_g + (size_t)r * K_GEMM + k0 + q * 8;
            const __nv_bfloat16* sa_l = Alo_g + (size_t)r * K_GEMM + k0 + q * 8;
            const __nv_bfloat16* sb_h = Bhi_g + (size_t)r * CIN + k0 + q * 8;
            const __nv_bfloat16* sb_l = Blo_g + (size_t)r * CIN + k0 + q * 8;
            CP16(sb + doff,              sa_h);
            CP16(sb + TILE_B + doff,     sa_l);
            CP16(sb + 2 * TILE_B + doff, sb_h);
            CP16(sb + 3 * TILE_B + doff, sb_l);
        }
        CP_COMMIT();
    };

    float acc[4][4][4] = {};   // [mf][jj][reg]

    // ldmatrix lane-address components
    const int arow = warp_m * 64 + (lane & 15);      // + mf*16
    const int acol = (lane & 16);                    // 0 or 16 bytes (k +8 elems)
    const int nloc = ((lane >> 4) & 1) * 8 + (lane & 7); // + jjpair*16 + warp_n*32
    const int bcol = ((lane >> 3) & 1) * 16;         // 0 or 16 bytes

    copy_chunk(0);
    copy_chunk(1);

    for (int ch = 0; ch < NCHUNK; ch++) {
        if (ch < NCHUNK - 1) { CP_WAIT(1); } else { CP_WAIT(0); }
        __syncthreads();

        const uint32_t sb   = sbase + (ch & 1) * STAGE_B;
        const uint32_t tAhi = sb;
        const uint32_t tAlo = sb + TILE_B;
        const uint32_t tBhi = sb + 2 * TILE_B;
        const uint32_t tBlo = sb + 3 * TILE_B;

#pragma unroll
        for (int kf = 0; kf < BK / 16; kf++) {
            uint32_t ahi[4][4], alo[4][4];
#pragma unroll
            for (int mf = 0; mf < 4; mf++) {
                uint32_t off = swz((uint32_t)((arow + mf * 16) * 128 + kf * 32 + acol));
                ldsm_x4(ahi[mf], tAhi + off);
                ldsm_x4(alo[mf], tAlo + off);
            }
            uint32_t bhi[4][2], blo[4][2];
#pragma unroll
            for (int jp = 0; jp < 2; jp++) {   // jj pair: (2jp, 2jp+1)
                uint32_t off = swz((uint32_t)((warp_n * 32 + jp * 16 + nloc) * 128 + kf * 32 + bcol));
                uint32_t rh[4], rl[4];
                ldsm_x4(rh, tBhi + off);
                ldsm_x4(rl, tBlo + off);
                bhi[2*jp][0] = rh[0]; bhi[2*jp][1] = rh[1];
                bhi[2*jp+1][0] = rh[2]; bhi[2*jp+1][1] = rh[3];
                blo[2*jp][0] = rl[0]; blo[2*jp][1] = rl[1];
                blo[2*jp+1][0] = rl[2]; blo[2*jp+1][1] = rl[3];
            }
#pragma unroll
            for (int mf = 0; mf < 4; mf++)
#pragma unroll
                for (int jj = 0; jj < 4; jj++) {
                    mma_bf16(acc[mf][jj], ahi[mf], bhi[jj]);
                    mma_bf16(acc[mf][jj], ahi[mf], blo[jj]);
                    mma_bf16(acc[mf][jj], alo[mf], bhi[jj]);
                }
        }

        if (ch + 2 < NCHUNK) {
            __syncthreads();
            copy_chunk(ch + 2);
        }
    }

    // ---- epilogue ----
    float* Gout = g_G + (size_t)b * M_GEMM * HW;
    const int rbase = m0 + warp_m * 64 + (lane >> 2);
    const int cbase = n0 + warp_n * 32 + (lane & 3) * 2;
#pragma unroll
    for (int mf = 0; mf < 4; mf++) {
#pragma unroll
        for (int jj = 0; jj < 4; jj++) {
            int r = rbase + mf * 16;
            int c = cbase + jj * 8;
            *reinterpret_cast<float2*>(&Gout[(size_t)r * HW + c]) =
                make_float2(acc[mf][jj][0], acc[mf][jj][1]);
            *reinterpret_cast<float2*>(&Gout[(size_t)(r + 8) * HW + c]) =
                make_float2(acc[mf][jj][2], acc[mf][jj][3]);
        }
    }
}

// ---------------------------------------------------------------------------
// Kernel 4: combine — bilinear gather of G with per-corner coeffs * mask
// ---------------------------------------------------------------------------
#define TP 128
__global__ __launch_bounds__(TP) void combine_kernel(
    const float* __restrict__ offset,
    const float* __restrict__ mask,
    const float* __restrict__ bias,
    float* __restrict__ out)
{
    __shared__ int4   s_idx[TP * K2];
    __shared__ float4 s_cw[TP * K2];
    __shared__ float  s_bias[COUT];

    const int b   = blockIdx.y;
    const int p0  = blockIdx.x * TP;
    const int tid = threadIdx.x;

    for (int i = tid; i < COUT; i += TP) s_bias[i] = bias[i];

    for (int e = tid; e < TP * K2; e += TP) {
        int lp = e / K2;
        int k  = e - lp * K2;
        int p  = p0 + lp;
        int py = p >> 6;
        int px = p & 63;

        float dy = offset[((b * 2 * K2) + 2 * k    ) * HW + p];
        float dx = offset[((b * 2 * K2) + 2 * k + 1) * HW + p];
        float m  = mask[(b * K2 + k) * HW + p];

        float yy = (float)(py - 1 + (k / 3)) + dy;
        float xx = (float)(px - 1 + (k % 3)) + dx;

        float y0f = floorf(yy), x0f = floorf(xx);
        float ly = yy - y0f, lx = xx - x0f;
        float hy = 1.0f - ly, hx = 1.0f - lx;
        int y0 = (int)y0f, x0 = (int)x0f;
        int y1 = y0 + 1,   x1 = x0 + 1;

        bool vy0 = (y0 >= 0) && (y0 < HDIM);
        bool vy1 = (y1 >= 0) && (y1 < HDIM);
        bool vx0 = (x0 >= 0) && (x0 < WDIM);
        bool vx1 = (x1 >= 0) && (x1 < WDIM);

        int cy0 = min(max(y0, 0), HDIM - 1);
        int cy1 = min(max(y1, 0), HDIM - 1);
        int cx0 = min(max(x0, 0), WDIM - 1);
        int cx1 = min(max(x1, 0), WDIM - 1);

        s_idx[e] = make_int4(cy0 * WDIM + cx0, cy0 * WDIM + cx1,
                             cy1 * WDIM + cx0, cy1 * WDIM + cx1);
        s_cw[e]  = make_float4((vy0 && vx0) ? hy * hx * m : 0.0f,
                               (vy0 && vx1) ? hy * lx * m : 0.0f,
                               (vy1 && vx0) ? ly * hx * m : 0.0f,
                               (vy1 && vx1) ? ly * lx * m : 0.0f);
    }
    __syncthreads();

    const int p = p0 + tid;
    for (int o = 0; o < COUT; o += 4) {
        float a0 = s_bias[o + 0];
        float a1 = s_bias[o + 1];
        float a2 = s_bias[o + 2];
        float a3 = s_bias[o + 3];
#pragma unroll
        for (int k = 0; k < K2; k++) {
            int4   id = s_idx[tid * K2 + k];
            float4 cw = s_cw[tid * K2 + k];
            const float* Gb = g_G + ((size_t)((b * K2 + k) * COUT + o)) * HW;
            const float* G0 = Gb;
            const float* G1 = Gb + HW;
            const float* G2 = Gb + 2 * HW;
            const float* G3 = Gb + 3 * HW;
            a0 += cw.x * G0[id.x] + cw.y * G0[id.y] + cw.z * G0[id.z] + cw.w * G0[id.w];
            a1 += cw.x * G1[id.x] + cw.y * G1[id.y] + cw.z * G1[id.z] + cw.w * G1[id.w];
            a2 += cw.x * G2[id.x] + cw.y * G2[id.y] + cw.z * G2[id.z] + cw.w * G2[id.w];
            a3 += cw.x * G3[id.x] + cw.y * G3[id.y] + cw.z * G3[id.z] + cw.w * G3[id.w];
        }
        out[((size_t)(b * COUT + o + 0)) * HW + p] = a0;
        out[((size_t)(b * COUT + o + 1)) * HW + p] = a1;
        out[((size_t)(b * COUT + o + 2)) * HW + p] = a2;
        out[((size_t)(b * COUT + o + 3)) * HW + p] = a3;
    }
}

// ---------------------------------------------------------------------------
extern "C" void kernel_launch(void* const* d_in, const int* in_sizes, int n_in,
                              void* d_out, int out_size) {
    const float* x      = (const float*)d_in[0];   // [4,256,64,64]
    const float* offset = (const float*)d_in[1];   // [4,18,64,64]
    const float* mask   = (const float*)d_in[2];   // [4,9,64,64]
    const float* weight = (const float*)d_in[3];   // [256,256,3,3]
    const float* bias   = (const float*)d_in[4];   // [256]
    float* out = (float*)d_out;                    // [4,256,64,64]

    static bool attr_set = false;
    if (!attr_set) {
        cudaFuncSetAttribute(gemm_bf16_kernel,
                             cudaFuncAttributeMaxDynamicSharedMemorySize, SMEM_DYN);
        attr_set = true;
    }

    blend_weights_kernel<<<(COUT * CIN + 255) / 256, 256>>>(weight);
    transpose_split_kernel<<<dim3(HW / 32, CIN / 32, BATCH), dim3(32, 8)>>>(x);
    gemm_bf16_kernel<<<dim3(HW / BN, M_GEMM / BM, BATCH), 256, SMEM_DYN>>>();
    combine_kernel<<<dim3(HW / TP, BATCH), TP>>>(offset, mask, bias, out);
}

// round 4
// speedup vs baseline: 3.1384x; 1.6951x over previous
#include <cuda_runtime.h>
#include <cuda_bf16.h>
#include <cstdint>

// ---------------- problem constants ----------------
#define CIN    256
#define COUT   256
#define HDIM   64
#define WDIM   64
#define BATCH  4
#define K2     9
#define HW     4096
#define M_GEMM 2304          // K2 * COUT
#define K_GEMM 256           // CIN

// ---------------- GEMM tiling ----------------
#define BM 128                         // n-tile rows
#define BN 128                         // m-tile cols
#define BK 64                          // bf16 elements per chunk (128B rows)
#define NCHUNK (K_GEMM / BK)           // 4
#define TILE_B (BM * BK * 2)           // 16384 bytes per operand tile
#define STAGE_B (4 * TILE_B)           // Ahi, Alo, Bhi, Blo = 64 KB
#define SMEM_DYN (2 * STAGE_B)         // 128 KB

// ---------------- scratch (device globals) ----------------
__device__ __nv_bfloat16 g_Whi[M_GEMM * K_GEMM];     // [m][c]
__device__ __nv_bfloat16 g_Wlo[M_GEMM * K_GEMM];
__device__ __nv_bfloat16 g_Xhi[BATCH * HW * CIN];    // [b][n][c]
__device__ __nv_bfloat16 g_Xlo[BATCH * HW * CIN];
// NOTE layout: G[b][k][n][o]  (o contiguous!)  151 MB
__device__ float g_G[(size_t)BATCH * K2 * HW * COUT];

// ---------------- PTX helpers ----------------
__device__ __forceinline__ uint32_t smem_u32(const void* p) {
    uint32_t a;
    asm("{ .reg .u64 t; cvta.to.shared.u64 t, %1; cvt.u32.u64 %0, t; }" : "=r"(a) : "l"(p));
    return a;
}
#define CP16(dst, src)  asm volatile("cp.async.cg.shared.global [%0], [%1], 16;" :: "r"(dst), "l"(src) : "memory")
#define CP_COMMIT()     asm volatile("cp.async.commit_group;" ::: "memory")
#define CP_WAIT(n)      asm volatile("cp.async.wait_group %0;" :: "n"(n) : "memory")

__device__ __forceinline__ void ldsm_x4(uint32_t* r, uint32_t addr) {
    asm volatile("ldmatrix.sync.aligned.m8n8.x4.shared.b16 {%0,%1,%2,%3}, [%4];"
                 : "=r"(r[0]), "=r"(r[1]), "=r"(r[2]), "=r"(r[3]) : "r"(addr));
}
__device__ __forceinline__ void mma_bf16(float* d, const uint32_t* a, const uint32_t* b) {
    asm volatile("mma.sync.aligned.m16n8k16.row.col.f32.bf16.bf16.f32 "
                 "{%0,%1,%2,%3}, {%4,%5,%6,%7}, {%8,%9}, {%0,%1,%2,%3};"
                 : "+f"(d[0]), "+f"(d[1]), "+f"(d[2]), "+f"(d[3])
                 : "r"(a[0]), "r"(a[1]), "r"(a[2]), "r"(a[3]), "r"(b[0]), "r"(b[1]));
}
__device__ __forceinline__ uint32_t swz(uint32_t off) { return off ^ ((off >> 3) & 0x70); }

// ---------------------------------------------------------------------------
// Kernel 1: circle-blend weights, split into bf16 hi/lo, store K-major [m][c]
// ---------------------------------------------------------------------------
__global__ void blend_weights_kernel(const float* __restrict__ weight) {
    int t = blockIdx.x * blockDim.x + threadIdx.x;
    if (t >= COUT * CIN) return;
    int o = t >> 8;
    int c = t & 255;
    const float* wp = weight + ((size_t)(o * CIN + c)) * K2;
    float w0 = wp[0], w1 = wp[1], w2 = wp[2];
    float w3 = wp[3], w4 = wp[4], w5 = wp[5];
    float w6 = wp[6], w7 = wp[7], w8 = wp[8];

    const float A  = 0.7071067811865476f;
    const float Bc = 1.0f - 0.7071067811865476f;

    float t01 = A * w0 + Bc * w1;
    float t34 = A * w3 + Bc * w4;
    float t12 = Bc * w1 + A * w2;
    float t45 = Bc * w4 + A * w5;
    float t67 = A * w6 + Bc * w7;
    float t78 = Bc * w7 + A * w8;

    float nw[K2];
    nw[0] = A * t01 + Bc * t34;  nw[1] = w1;
    nw[2] = A * t12 + Bc * t45;  nw[3] = w3;  nw[4] = w4;  nw[5] = w5;
    nw[6] = Bc * t34 + A * t67;  nw[7] = w7;
    nw[8] = Bc * t45 + A * t78;

#pragma unroll
    for (int k = 0; k < K2; k++) {
        float v = nw[k];
        __nv_bfloat16 hi = __float2bfloat16_rn(v);
        float lo = v - __bfloat162float(hi);
        size_t idx = (size_t)(k * COUT + o) * K_GEMM + c;
        g_Whi[idx] = hi;
        g_Wlo[idx] = __float2bfloat16_rn(lo);
    }
}

// ---------------------------------------------------------------------------
// Kernel 2: transpose x[b][c][n] -> Xt[b][n][c], split bf16 hi/lo
// ---------------------------------------------------------------------------
__global__ __launch_bounds__(256) void transpose_split_kernel(const float* __restrict__ X) {
    __shared__ float t[32][33];
    int b  = blockIdx.z;
    int n0 = blockIdx.x * 32;
    int c0 = blockIdx.y * 32;
    int tx = threadIdx.x, ty = threadIdx.y;

    const float* src = X + ((size_t)b * CIN + c0) * HW + n0;
#pragma unroll
    for (int i = ty; i < 32; i += 8)
        t[i][tx] = src[(size_t)i * HW + tx];
    __syncthreads();

    __nv_bfloat16* dhi = g_Xhi + ((size_t)b * HW + n0) * CIN + c0;
    __nv_bfloat16* dlo = g_Xlo + ((size_t)b * HW + n0) * CIN + c0;
#pragma unroll
    for (int i = ty; i < 32; i += 8) {
        float v = t[tx][i];
        __nv_bfloat16 hi = __float2bfloat16_rn(v);
        float lo = v - __bfloat162float(hi);
        dhi[(size_t)i * CIN + tx] = hi;
        dlo[(size_t)i * CIN + tx] = __float2bfloat16_rn(lo);
    }
}

// ---------------------------------------------------------------------------
// Kernel 3: bf16x2 split GEMM (operand roles swapped: A = Xt rows n, B = W rows m)
//   G[b][k][n][o] = sum_c Xt[b][n][c] * W[k*256+o][c]
// ---------------------------------------------------------------------------
extern __shared__ __align__(1024) unsigned char dsmem[];

__global__ __launch_bounds__(256, 1) void gemm_bf16_kernel() {
    const int tid  = threadIdx.x;
    const int wid  = tid >> 5;
    const int lane = tid & 31;
    const int warp_m = wid >> 2;       // 0..1  (64 n-rows each)
    const int warp_n = wid & 3;        // 0..3  (32 m-cols each)

    const int b  = blockIdx.z;
    const int n0 = blockIdx.x * BM;    // n tile (A rows)
    const int m0 = blockIdx.y * BN;    // m tile (B rows)

    const uint32_t sbase = smem_u32(dsmem);

    // A = Xt (rows n), B = W (rows m); both row stride 256 bf16
    const __nv_bfloat16* Ahi_g = g_Xhi + ((size_t)b * HW + n0) * CIN;
    const __nv_bfloat16* Alo_g = g_Xlo + ((size_t)b * HW + n0) * CIN;
    const __nv_bfloat16* Bhi_g = g_Whi + (size_t)m0 * K_GEMM;
    const __nv_bfloat16* Blo_g = g_Wlo + (size_t)m0 * K_GEMM;

    auto copy_chunk = [&](int ch) {
        const uint32_t sb = sbase + (ch & 1) * STAGE_B;
        const int k0 = ch * BK;
#pragma unroll
        for (int t = 0; t < 4; t++) {
            int u = t * 256 + tid;          // 0..1023
            int r = u >> 3;                 // row 0..127
            int q = u & 7;                  // 16B unit in row
            uint32_t doff = swz((uint32_t)(r * 128 + q * 16));
            const __nv_bfloat16* sa_h = Ahi_g + (size_t)r * CIN    + k0 + q * 8;
            const __nv_bfloat16* sa_l = Alo_g + (size_t)r * CIN    + k0 + q * 8;
            const __nv_bfloat16* sb_h = Bhi_g + (size_t)r * K_GEMM + k0 + q * 8;
            const __nv_bfloat16* sb_l = Blo_g + (size_t)r * K_GEMM + k0 + q * 8;
            CP16(sb + doff,              sa_h);
            CP16(sb + TILE_B + doff,     sa_l);
            CP16(sb + 2 * TILE_B + doff, sb_h);
            CP16(sb + 3 * TILE_B + doff, sb_l);
        }
        CP_COMMIT();
    };

    float acc[4][4][4] = {};   // [mf][jj][reg]

    const int arow = warp_m * 64 + (lane & 15);
    const int acol = (lane & 16);
    const int nloc = ((lane >> 4) & 1) * 8 + (lane & 7);
    const int bcol = ((lane >> 3) & 1) * 16;

    copy_chunk(0);
    copy_chunk(1);

    for (int ch = 0; ch < NCHUNK; ch++) {
        if (ch < NCHUNK - 1) { CP_WAIT(1); } else { CP_WAIT(0); }
        __syncthreads();

        const uint32_t sb   = sbase + (ch & 1) * STAGE_B;
        const uint32_t tAhi = sb;
        const uint32_t tAlo = sb + TILE_B;
        const uint32_t tBhi = sb + 2 * TILE_B;
        const uint32_t tBlo = sb + 3 * TILE_B;

#pragma unroll
        for (int kf = 0; kf < BK / 16; kf++) {
            uint32_t ahi[4][4], alo[4][4];
#pragma unroll
            for (int mf = 0; mf < 4; mf++) {
                uint32_t off = swz((uint32_t)((arow + mf * 16) * 128 + kf * 32 + acol));
                ldsm_x4(ahi[mf], tAhi + off);
                ldsm_x4(alo[mf], tAlo + off);
            }
            uint32_t bhi[4][2], blo[4][2];
#pragma unroll
            for (int jp = 0; jp < 2; jp++) {
                uint32_t off = swz((uint32_t)((warp_n * 32 + jp * 16 + nloc) * 128 + kf * 32 + bcol));
                uint32_t rh[4], rl[4];
                ldsm_x4(rh, tBhi + off);
                ldsm_x4(rl, tBlo + off);
                bhi[2*jp][0] = rh[0]; bhi[2*jp][1] = rh[1];
                bhi[2*jp+1][0] = rh[2]; bhi[2*jp+1][1] = rh[3];
                blo[2*jp][0] = rl[0]; blo[2*jp][1] = rl[1];
                blo[2*jp+1][0] = rl[2]; blo[2*jp+1][1] = rl[3];
            }
#pragma unroll
            for (int mf = 0; mf < 4; mf++)
#pragma unroll
                for (int jj = 0; jj < 4; jj++) {
                    mma_bf16(acc[mf][jj], ahi[mf], bhi[jj]);
                    mma_bf16(acc[mf][jj], ahi[mf], blo[jj]);
                    mma_bf16(acc[mf][jj], alo[mf], bhi[jj]);
                }
        }

        if (ch + 2 < NCHUNK) {
            __syncthreads();
            copy_chunk(ch + 2);
        }
    }

    // ---- epilogue: rows = n, cols = o (m within fixed tap k) ----
    const int k_blk = m0 >> 8;          // tap index
    const int o0    = m0 & 255;         // o base (0 or 128)
    float* Gout = g_G + ((size_t)(b * K2 + k_blk)) * HW * COUT;

    const int rbase = n0 + warp_m * 64 + (lane >> 2);          // n
    const int cbase = o0 + warp_n * 32 + (lane & 3) * 2;       // o
#pragma unroll
    for (int mf = 0; mf < 4; mf++) {
#pragma unroll
        for (int jj = 0; jj < 4; jj++) {
            int n = rbase + mf * 16;
            int o = cbase + jj * 8;
            *reinterpret_cast<float2*>(&Gout[(size_t)n * COUT + o]) =
                make_float2(acc[mf][jj][0], acc[mf][jj][1]);
            *reinterpret_cast<float2*>(&Gout[(size_t)(n + 8) * COUT + o]) =
                make_float2(acc[mf][jj][2], acc[mf][jj][3]);
        }
    }
}

// ---------------------------------------------------------------------------
// Kernel 4: combine — coalesced bilinear gather over G[b][k][n][o]
//   1 warp per pixel, 8 pixels per CTA; lane owns 8 o-channels.
// ---------------------------------------------------------------------------
#define PPB 8
__global__ __launch_bounds__(256) void combine_kernel(
    const float* __restrict__ offset,
    const float* __restrict__ mask,
    const float* __restrict__ bias,
    float* __restrict__ out)
{
    __shared__ int4   s_idx[PPB][K2];
    __shared__ float4 s_cw[PPB][K2];
    __shared__ float  s_out[PPB][COUT];   // [px][o], 8 KB

    const int b    = blockIdx.y;
    const int p0   = blockIdx.x * PPB;
    const int tid  = threadIdx.x;
    const int w    = tid >> 5;
    const int lane = tid & 31;
    const int p    = p0 + w;

    // Phase 1: lanes 0..8 compute per-tap corner indices + coefficients
    if (lane < K2) {
        const int k  = lane;
        const int py = p >> 6;
        const int px = p & 63;

        float dy = offset[((b * 2 * K2) + 2 * k    ) * HW + p];
        float dx = offset[((b * 2 * K2) + 2 * k + 1) * HW + p];
        float m  = mask[(b * K2 + k) * HW + p];

        float yy = (float)(py - 1 + (k / 3)) + dy;
        float xx = (float)(px - 1 + (k % 3)) + dx;

        float y0f = floorf(yy), x0f = floorf(xx);
        float ly = yy - y0f, lx = xx - x0f;
        float hy = 1.0f - ly, hx = 1.0f - lx;
        int y0 = (int)y0f, x0 = (int)x0f;
        int y1 = y0 + 1,   x1 = x0 + 1;

        bool vy0 = (y0 >= 0) && (y0 < HDIM);
        bool vy1 = (y1 >= 0) && (y1 < HDIM);
        bool vx0 = (x0 >= 0) && (x0 < WDIM);
        bool vx1 = (x1 >= 0) && (x1 < WDIM);

        int cy0 = min(max(y0, 0), HDIM - 1);
        int cy1 = min(max(y1, 0), HDIM - 1);
        int cx0 = min(max(x0, 0), WDIM - 1);
        int cx1 = min(max(x1, 0), WDIM - 1);

        s_idx[w][k] = make_int4(cy0 * WDIM + cx0, cy0 * WDIM + cx1,
                                cy1 * WDIM + cx0, cy1 * WDIM + cx1);
        s_cw[w][k]  = make_float4((vy0 && vx0) ? hy * hx * m : 0.0f,
                                  (vy0 && vx1) ? hy * lx * m : 0.0f,
                                  (vy1 && vx0) ? ly * hx * m : 0.0f,
                                  (vy1 && vx1) ? ly * lx * m : 0.0f);
    }
    __syncwarp();

    // Phase 2: accumulate 8 o-channels per lane (o = lane*8 .. +8)
    const int o8 = lane * 8;
    float acc[8];
    {
        const float4* b4 = reinterpret_cast<const float4*>(bias + o8);
        float4 b0 = b4[0], b1 = b4[1];
        acc[0] = b0.x; acc[1] = b0.y; acc[2] = b0.z; acc[3] = b0.w;
        acc[4] = b1.x; acc[5] = b1.y; acc[6] = b1.z; acc[7] = b1.w;
    }

#pragma unroll
    for (int k = 0; k < K2; k++) {
        int4   id = s_idx[w][k];
        float4 cw = s_cw[w][k];
        const float* base = g_G + ((size_t)(b * K2 + k)) * HW * COUT + o8;

        const float4* q0 = reinterpret_cast<const float4*>(base + (size_t)id.x * COUT);
        const float4* q1 = reinterpret_cast<const float4*>(base + (size_t)id.y * COUT);
        const float4* q2 = reinterpret_cast<const float4*>(base + (size_t)id.z * COUT);
        const float4* q3 = reinterpret_cast<const float4*>(base + (size_t)id.w * COUT);
        float4 a0 = q0[0], a1 = q0[1];
        float4 b0 = q1[0], b1 = q1[1];
        float4 c0 = q2[0], c1 = q2[1];
        float4 d0 = q3[0], d1 = q3[1];

        acc[0] += cw.x * a0.x + cw.y * b0.x + cw.z * c0.x + cw.w * d0.x;
        acc[1] += cw.x * a0.y + cw.y * b0.y + cw.z * c0.y + cw.w * d0.y;
        acc[2] += cw.x * a0.z + cw.y * b0.z + cw.z * c0.z + cw.w * d0.z;
        acc[3] += cw.x * a0.w + cw.y * b0.w + cw.z * c0.w + cw.w * d0.w;
        acc[4] += cw.x * a1.x + cw.y * b1.x + cw.z * c1.x + cw.w * d1.x;
        acc[5] += cw.x * a1.y + cw.y * b1.y + cw.z * c1.y + cw.w * d1.y;
        acc[6] += cw.x * a1.z + cw.y * b1.z + cw.z * c1.z + cw.w * d1.z;
        acc[7] += cw.x * a1.w + cw.y * b1.w + cw.z * c1.w + cw.w * d1.w;
    }

    // Stage to smem for coalesced output writes
#pragma unroll
    for (int j = 0; j < 8; j++) s_out[w][o8 + j] = acc[j];
    __syncthreads();

    // Phase 3: thread t writes out[b][o=t][p0..p0+8] as 2x float4 (32B)
    {
        const int o = tid;
        float4 r0 = make_float4(s_out[0][o], s_out[1][o], s_out[2][o], s_out[3][o]);
        float4 r1 = make_float4(s_out[4][o], s_out[5][o], s_out[6][o], s_out[7][o]);
        float* dst = out + ((size_t)(b * COUT + o)) * HW + p0;
        *reinterpret_cast<float4*>(dst)     = r0;
        *reinterpret_cast<float4*>(dst + 4) = r1;
    }
}

// ---------------------------------------------------------------------------
extern "C" void kernel_launch(void* const* d_in, const int* in_sizes, int n_in,
                              void* d_out, int out_size) {
    const float* x      = (const float*)d_in[0];   // [4,256,64,64]
    const float* offset = (const float*)d_in[1];   // [4,18,64,64]
    const float* mask   = (const float*)d_in[2];   // [4,9,64,64]
    const float* weight = (const float*)d_in[3];   // [256,256,3,3]
    const float* bias   = (const float*)d_in[4];   // [256]
    float* out = (float*)d_out;                    // [4,256,64,64]

    static bool attr_set = false;
    if (!attr_set) {
        cudaFuncSetAttribute(gemm_bf16_kernel,
                             cudaFuncAttributeMaxDynamicSharedMemorySize, SMEM_DYN);
        attr_set = true;
    }

    blend_weights_kernel<<<(COUT * CIN + 255) / 256, 256>>>(weight);
    transpose_split_kernel<<<dim3(HW / 32, CIN / 32, BATCH), dim3(32, 8)>>>(x);
    gemm_bf16_kernel<<<dim3(HW / BM, M_GEMM / BN, BATCH), 256, SMEM_DYN>>>();
    combine_kernel<<<dim3(HW / PPB, BATCH), 256>>>(offset, mask, bias, out);
}

// round 5
// speedup vs baseline: 3.7707x; 1.2015x over previous
#include <cuda_runtime.h>
#include <cuda_fp16.h>
#include <cstdint>

// ---------------- problem constants ----------------
#define CIN    256
#define COUT   256
#define HDIM   64
#define WDIM   64
#define BATCH  4
#define K2     9
#define HW     4096
#define M_GEMM 2304          // K2 * COUT
#define K_GEMM 256           // CIN
#define WSCALE 256.0f
#define INV_WSCALE (1.0f / 256.0f)

// ---------------- GEMM tiling ----------------
#define BM 128                         // n-tile rows
#define BN 128                         // m-tile cols
#define BK 64                          // fp16 elements per chunk (128B rows)
#define NCHUNK (K_GEMM / BK)           // 4
#define TILE_B (BM * BK * 2)           // 16384 bytes per operand tile
#define STAGE_B (3 * TILE_B)           // A, Bhi, Blo = 48 KB
#define SMEM_DYN (2 * STAGE_B)         // 96 KB

// ---------------- scratch (device globals) ----------------
__device__ __half g_Whi[M_GEMM * K_GEMM];     // [m][c]  (scaled by 256)
__device__ __half g_Wlo[M_GEMM * K_GEMM];
__device__ __half g_Xh [BATCH * HW * CIN];    // [b][n][c]
// layout: G[b][k][n][o]  (o contiguous), values scaled by 256.  151 MB
__device__ float g_G[(size_t)BATCH * K2 * HW * COUT];

// ---------------- PTX helpers ----------------
__device__ __forceinline__ uint32_t smem_u32(const void* p) {
    uint32_t a;
    asm("{ .reg .u64 t; cvta.to.shared.u64 t, %1; cvt.u32.u64 %0, t; }" : "=r"(a) : "l"(p));
    return a;
}
#define CP16(dst, src)  asm volatile("cp.async.cg.shared.global [%0], [%1], 16;" :: "r"(dst), "l"(src) : "memory")
#define CP_COMMIT()     asm volatile("cp.async.commit_group;" ::: "memory")
#define CP_WAIT(n)      asm volatile("cp.async.wait_group %0;" :: "n"(n) : "memory")

__device__ __forceinline__ void ldsm_x4(uint32_t* r, uint32_t addr) {
    asm volatile("ldmatrix.sync.aligned.m8n8.x4.shared.b16 {%0,%1,%2,%3}, [%4];"
                 : "=r"(r[0]), "=r"(r[1]), "=r"(r[2]), "=r"(r[3]) : "r"(addr));
}
__device__ __forceinline__ void mma_fp16(float* d, const uint32_t* a, const uint32_t* b) {
    asm volatile("mma.sync.aligned.m16n8k16.row.col.f32.f16.f16.f32 "
                 "{%0,%1,%2,%3}, {%4,%5,%6,%7}, {%8,%9}, {%0,%1,%2,%3};"
                 : "+f"(d[0]), "+f"(d[1]), "+f"(d[2]), "+f"(d[3])
                 : "r"(a[0]), "r"(a[1]), "r"(a[2]), "r"(a[3]), "r"(b[0]), "r"(b[1]));
}
__device__ __forceinline__ uint32_t swz(uint32_t off) { return off ^ ((off >> 3) & 0x70); }

// ---------------------------------------------------------------------------
// Kernel 1: circle-blend weights, scale by 256, split into fp16 hi/lo, [m][c]
// ---------------------------------------------------------------------------
__global__ void blend_weights_kernel(const float* __restrict__ weight) {
    int t = blockIdx.x * blockDim.x + threadIdx.x;
    if (t >= COUT * CIN) return;
    int o = t >> 8;
    int c = t & 255;
    const float* wp = weight + ((size_t)(o * CIN + c)) * K2;
    float w0 = wp[0], w1 = wp[1], w2 = wp[2];
    float w3 = wp[3], w4 = wp[4], w5 = wp[5];
    float w6 = wp[6], w7 = wp[7], w8 = wp[8];

    const float A  = 0.7071067811865476f;
    const float Bc = 1.0f - 0.7071067811865476f;

    float t01 = A * w0 + Bc * w1;
    float t34 = A * w3 + Bc * w4;
    float t12 = Bc * w1 + A * w2;
    float t45 = Bc * w4 + A * w5;
    float t67 = A * w6 + Bc * w7;
    float t78 = Bc * w7 + A * w8;

    float nw[K2];
    nw[0] = A * t01 + Bc * t34;  nw[1] = w1;
    nw[2] = A * t12 + Bc * t45;  nw[3] = w3;  nw[4] = w4;  nw[5] = w5;
    nw[6] = Bc * t34 + A * t67;  nw[7] = w7;
    nw[8] = Bc * t45 + A * t78;

#pragma unroll
    for (int k = 0; k < K2; k++) {
        float v = nw[k] * WSCALE;
        __half hi = __float2half_rn(v);
        float lo = v - __half2float(hi);
        size_t idx = (size_t)(k * COUT + o) * K_GEMM + c;
        g_Whi[idx] = hi;
        g_Wlo[idx] = __float2half_rn(lo);
    }
}

// ---------------------------------------------------------------------------
// Kernel 2: transpose x[b][c][n] -> Xt[b][n][c] in fp16
// ---------------------------------------------------------------------------
__global__ __launch_bounds__(256) void transpose_split_kernel(const float* __restrict__ X) {
    __shared__ float t[32][33];
    int b  = blockIdx.z;
    int n0 = blockIdx.x * 32;
    int c0 = blockIdx.y * 32;
    int tx = threadIdx.x, ty = threadIdx.y;

    const float* src = X + ((size_t)b * CIN + c0) * HW + n0;
#pragma unroll
    for (int i = ty; i < 32; i += 8)
        t[i][tx] = src[(size_t)i * HW + tx];
    __syncthreads();

    __half* dh = g_Xh + ((size_t)b * HW + n0) * CIN + c0;
#pragma unroll
    for (int i = ty; i < 32; i += 8)
        dh[(size_t)i * CIN + tx] = __float2half_rn(t[tx][i]);
}

// ---------------------------------------------------------------------------
// Kernel 3: fp16 2-pass GEMM (A = Xt rows n, B = W rows m)
//   G[b][k][n][o] = sum_c Xh[b][n][c] * (Whi + Wlo)[k*256+o][c]
// ---------------------------------------------------------------------------
extern __shared__ __align__(1024) unsigned char dsmem[];

__global__ __launch_bounds__(256, 1) void gemm_fp16_kernel() {
    const int tid  = threadIdx.x;
    const int wid  = tid >> 5;
    const int lane = tid & 31;
    const int warp_m = wid >> 2;       // 0..1  (64 n-rows each)
    const int warp_n = wid & 3;        // 0..3  (32 m-cols each)

    const int b  = blockIdx.z;
    const int n0 = blockIdx.x * BM;    // n tile (A rows)
    const int m0 = blockIdx.y * BN;    // m tile (B rows)

    const uint32_t sbase = smem_u32(dsmem);

    const __half* A_g   = g_Xh  + ((size_t)b * HW + n0) * CIN;
    const __half* Bhi_g = g_Whi + (size_t)m0 * K_GEMM;
    const __half* Blo_g = g_Wlo + (size_t)m0 * K_GEMM;

    auto copy_chunk = [&](int ch) {
        const uint32_t sb = sbase + (ch & 1) * STAGE_B;
        const int k0 = ch * BK;
#pragma unroll
        for (int t = 0; t < 4; t++) {
            int u = t * 256 + tid;          // 0..1023
            int r = u >> 3;                 // row 0..127
            int q = u & 7;                  // 16B unit in row
            uint32_t doff = swz((uint32_t)(r * 128 + q * 16));
            CP16(sb + doff,              A_g   + (size_t)r * CIN    + k0 + q * 8);
            CP16(sb + TILE_B + doff,     Bhi_g + (size_t)r * K_GEMM + k0 + q * 8);
            CP16(sb + 2 * TILE_B + doff, Blo_g + (size_t)r * K_GEMM + k0 + q * 8);
        }
        CP_COMMIT();
    };

    float acc[4][4][4] = {};   // [mf][jj][reg]

    const int arow = warp_m * 64 + (lane & 15);
    const int acol = (lane & 16);
    const int nloc = ((lane >> 4) & 1) * 8 + (lane & 7);
    const int bcol = ((lane >> 3) & 1) * 16;

    copy_chunk(0);
    copy_chunk(1);

    for (int ch = 0; ch < NCHUNK; ch++) {
        if (ch < NCHUNK - 1) { CP_WAIT(1); } else { CP_WAIT(0); }
        __syncthreads();

        const uint32_t sb   = sbase + (ch & 1) * STAGE_B;
        const uint32_t tA   = sb;
        const uint32_t tBhi = sb + TILE_B;
        const uint32_t tBlo = sb + 2 * TILE_B;

#pragma unroll
        for (int kf = 0; kf < BK / 16; kf++) {
            uint32_t af[4][4];
#pragma unroll
            for (int mf = 0; mf < 4; mf++) {
                uint32_t off = swz((uint32_t)((arow + mf * 16) * 128 + kf * 32 + acol));
                ldsm_x4(af[mf], tA + off);
            }
            uint32_t bhi[4][2], blo[4][2];
#pragma unroll
            for (int jp = 0; jp < 2; jp++) {
                uint32_t off = swz((uint32_t)((warp_n * 32 + jp * 16 + nloc) * 128 + kf * 32 + bcol));
                uint32_t rh[4], rl[4];
                ldsm_x4(rh, tBhi + off);
                ldsm_x4(rl, tBlo + off);
                bhi[2*jp][0] = rh[0]; bhi[2*jp][1] = rh[1];
                bhi[2*jp+1][0] = rh[2]; bhi[2*jp+1][1] = rh[3];
                blo[2*jp][0] = rl[0]; blo[2*jp][1] = rl[1];
                blo[2*jp+1][0] = rl[2]; blo[2*jp+1][1] = rl[3];
            }
#pragma unroll
            for (int mf = 0; mf < 4; mf++)
#pragma unroll
                for (int jj = 0; jj < 4; jj++) {
                    mma_fp16(acc[mf][jj], af[mf], bhi[jj]);
                    mma_fp16(acc[mf][jj], af[mf], blo[jj]);
                }
        }

        if (ch + 2 < NCHUNK) {
            __syncthreads();
            copy_chunk(ch + 2);
        }
    }

    // ---- epilogue: rows = n, cols = o (m within fixed tap k) ----
    const int k_blk = m0 >> 8;          // tap index
    const int o0    = m0 & 255;         // o base (0 or 128)
    float* Gout = g_G + ((size_t)(b * K2 + k_blk)) * HW * COUT;

    const int rbase = n0 + warp_m * 64 + (lane >> 2);          // n
    const int cbase = o0 + warp_n * 32 + (lane & 3) * 2;       // o
#pragma unroll
    for (int mf = 0; mf < 4; mf++) {
#pragma unroll
        for (int jj = 0; jj < 4; jj++) {
            int n = rbase + mf * 16;
            int o = cbase + jj * 8;
            *reinterpret_cast<float2*>(&Gout[(size_t)n * COUT + o]) =
                make_float2(acc[mf][jj][0], acc[mf][jj][1]);
            *reinterpret_cast<float2*>(&Gout[(size_t)(n + 8) * COUT + o]) =
                make_float2(acc[mf][jj][2], acc[mf][jj][3]);
        }
    }
}

// ---------------------------------------------------------------------------
// Kernel 4: combine — coalesced bilinear gather over G[b][k][n][o]
//   1 warp per pixel, 8 pixels per CTA; lane owns 8 o-channels.
//   Bilinear coeffs folded with mask and the 1/256 weight descale.
// ---------------------------------------------------------------------------
#define PPB 8
__global__ __launch_bounds__(256) void combine_kernel(
    const float* __restrict__ offset,
    const float* __restrict__ mask,
    const float* __restrict__ bias,
    float* __restrict__ out)
{
    __shared__ int4   s_idx[PPB][K2];
    __shared__ float4 s_cw[PPB][K2];
    __shared__ float  s_out[PPB][COUT];

    const int b    = blockIdx.y;
    const int p0   = blockIdx.x * PPB;
    const int tid  = threadIdx.x;
    const int w    = tid >> 5;
    const int lane = tid & 31;
    const int p    = p0 + w;

    if (lane < K2) {
        const int k  = lane;
        const int py = p >> 6;
        const int px = p & 63;

        float dy = offset[((b * 2 * K2) + 2 * k    ) * HW + p];
        float dx = offset[((b * 2 * K2) + 2 * k + 1) * HW + p];
        float m  = mask[(b * K2 + k) * HW + p] * INV_WSCALE;

        float yy = (float)(py - 1 + (k / 3)) + dy;
        float xx = (float)(px - 1 + (k % 3)) + dx;

        float y0f = floorf(yy), x0f = floorf(xx);
        float ly = yy - y0f, lx = xx - x0f;
        float hy = 1.0f - ly, hx = 1.0f - lx;
        int y0 = (int)y0f, x0 = (int)x0f;
        int y1 = y0 + 1,   x1 = x0 + 1;

        bool vy0 = (y0 >= 0) && (y0 < HDIM);
        bool vy1 = (y1 >= 0) && (y1 < HDIM);
        bool vx0 = (x0 >= 0) && (x0 < WDIM);
        bool vx1 = (x1 >= 0) && (x1 < WDIM);

        int cy0 = min(max(y0, 0), HDIM - 1);
        int cy1 = min(max(y1, 0), HDIM - 1);
        int cx0 = min(max(x0, 0), WDIM - 1);
        int cx1 = min(max(x1, 0), WDIM - 1);

        s_idx[w][k] = make_int4(cy0 * WDIM + cx0, cy0 * WDIM + cx1,
                                cy1 * WDIM + cx0, cy1 * WDIM + cx1);
        s_cw[w][k]  = make_float4((vy0 && vx0) ? hy * hx * m : 0.0f,
                                  (vy0 && vx1) ? hy * lx * m : 0.0f,
                                  (vy1 && vx0) ? ly * hx * m : 0.0f,
                                  (vy1 && vx1) ? ly * lx * m : 0.0f);
    }
    __syncwarp();

    const int o8 = lane * 8;
    float acc[8];
    {
        const float4* b4 = reinterpret_cast<const float4*>(bias + o8);
        float4 b0 = b4[0], b1 = b4[1];
        acc[0] = b0.x; acc[1] = b0.y; acc[2] = b0.z; acc[3] = b0.w;
        acc[4] = b1.x; acc[5] = b1.y; acc[6] = b1.z; acc[7] = b1.w;
    }

#pragma unroll
    for (int k = 0; k < K2; k++) {
        int4   id = s_idx[w][k];
        float4 cw = s_cw[w][k];
        const float* base = g_G + ((size_t)(b * K2 + k)) * HW * COUT + o8;

        const float4* q0 = reinterpret_cast<const float4*>(base + (size_t)id.x * COUT);
        const float4* q1 = reinterpret_cast<const float4*>(base + (size_t)id.y * COUT);
        const float4* q2 = reinterpret_cast<const float4*>(base + (size_t)id.z * COUT);
        const float4* q3 = reinterpret_cast<const float4*>(base + (size_t)id.w * COUT);
        float4 a0 = q0[0], a1 = q0[1];
        float4 b0 = q1[0], b1 = q1[1];
        float4 c0 = q2[0], c1 = q2[1];
        float4 d0 = q3[0], d1 = q3[1];

        acc[0] += cw.x * a0.x + cw.y * b0.x + cw.z * c0.x + cw.w * d0.x;
        acc[1] += cw.x * a0.y + cw.y * b0.y + cw.z * c0.y + cw.w * d0.y;
        acc[2] += cw.x * a0.z + cw.y * b0.z + cw.z * c0.z + cw.w * d0.z;
        acc[3] += cw.x * a0.w + cw.y * b0.w + cw.z * c0.w + cw.w * d0.w;
        acc[4] += cw.x * a1.x + cw.y * b1.x + cw.z * c1.x + cw.w * d1.x;
        acc[5] += cw.x * a1.y + cw.y * b1.y + cw.z * c1.y + cw.w * d1.y;
        acc[6] += cw.x * a1.z + cw.y * b1.z + cw.z * c1.z + cw.w * d1.z;
        acc[7] += cw.x * a1.w + cw.y * b1.w + cw.z * c1.w + cw.w * d1.w;
    }

#pragma unroll
    for (int j = 0; j < 8; j++) s_out[w][o8 + j] = acc[j];
    __syncthreads();

    {
        const int o = tid;
        float4 r0 = make_float4(s_out[0][o], s_out[1][o], s_out[2][o], s_out[3][o]);
        float4 r1 = make_float4(s_out[4][o], s_out[5][o], s_out[6][o], s_out[7][o]);
        float* dst = out + ((size_t)(b * COUT + o)) * HW + p0;
        *reinterpret_cast<float4*>(dst)     = r0;
        *reinterpret_cast<float4*>(dst + 4) = r1;
    }
}

// ---------------------------------------------------------------------------
extern "C" void kernel_launch(void* const* d_in, const int* in_sizes, int n_in,
                              void* d_out, int out_size) {
    const float* x      = (const float*)d_in[0];   // [4,256,64,64]
    const float* offset = (const float*)d_in[1];   // [4,18,64,64]
    const float* mask   = (const float*)d_in[2];   // [4,9,64,64]
    const float* weight = (const float*)d_in[3];   // [256,256,3,3]
    const float* bias   = (const float*)d_in[4];   // [256]
    float* out = (float*)d_out;                    // [4,256,64,64]

    static bool attr_set = false;
    if (!attr_set) {
        cudaFuncSetAttribute(gemm_fp16_kernel,
                             cudaFuncAttributeMaxDynamicSharedMemorySize, SMEM_DYN);
        attr_set = true;
    }

    blend_weights_kernel<<<(COUT * CIN + 255) / 256, 256>>>(weight);
    transpose_split_kernel<<<dim3(HW / 32, CIN / 32, BATCH), dim3(32, 8)>>>(x);
    gemm_fp16_kernel<<<dim3(HW / BM, M_GEMM / BN, BATCH), 256, SMEM_DYN>>>();
    combine_kernel<<<dim3(HW / PPB, BATCH), 256>>>(offset, mask, bias, out);
}

// round 6
// speedup vs baseline: 5.2868x; 1.4021x over previous
#include <cuda_runtime.h>
#include <cuda_fp16.h>
#include <cstdint>

// ---------------- problem constants ----------------
#define CIN    256
#define COUT   256
#define HDIM   64
#define WDIM   64
#define BATCH  4
#define K2     9
#define HW     4096
#define M_GEMM 2304          // K2 * COUT
#define K_GEMM 256           // CIN

// ---------------- GEMM tiling ----------------
#define BM 128                         // n-tile rows
#define BN 128                         // m-tile cols
#define BK 64                          // fp16 elements per chunk (128B rows)
#define NCHUNK (K_GEMM / BK)           // 4
#define TILE_B (BM * BK * 2)           // 16384 bytes per operand tile
#define STAGE_B (2 * TILE_B)           // A, B = 32 KB
#define SMEM_DYN (2 * STAGE_B)         // 64 KB

// ---------------- scratch (device globals) ----------------
__device__ __half g_Wh[M_GEMM * K_GEMM];      // [m][c]
__device__ __half g_Xh[BATCH * HW * CIN];     // [b][n][c]
// layout: G[b][k][n][o]  (o contiguous).  151 MB
__device__ float g_G[(size_t)BATCH * K2 * HW * COUT];

// ---------------- PTX helpers ----------------
__device__ __forceinline__ uint32_t smem_u32(const void* p) {
    uint32_t a;
    asm("{ .reg .u64 t; cvta.to.shared.u64 t, %1; cvt.u32.u64 %0, t; }" : "=r"(a) : "l"(p));
    return a;
}
#define CP16(dst, src)  asm volatile("cp.async.cg.shared.global [%0], [%1], 16;" :: "r"(dst), "l"(src) : "memory")
#define CP_COMMIT()     asm volatile("cp.async.commit_group;" ::: "memory")
#define CP_WAIT(n)      asm volatile("cp.async.wait_group %0;" :: "n"(n) : "memory")

__device__ __forceinline__ void ldsm_x4(uint32_t* r, uint32_t addr) {
    asm volatile("ldmatrix.sync.aligned.m8n8.x4.shared.b16 {%0,%1,%2,%3}, [%4];"
                 : "=r"(r[0]), "=r"(r[1]), "=r"(r[2]), "=r"(r[3]) : "r"(addr));
}
__device__ __forceinline__ void mma_fp16(float* d, const uint32_t* a, const uint32_t* b) {
    asm volatile("mma.sync.aligned.m16n8k16.row.col.f32.f16.f16.f32 "
                 "{%0,%1,%2,%3}, {%4,%5,%6,%7}, {%8,%9}, {%0,%1,%2,%3};"
                 : "+f"(d[0]), "+f"(d[1]), "+f"(d[2]), "+f"(d[3])
                 : "r"(a[0]), "r"(a[1]), "r"(a[2]), "r"(a[3]), "r"(b[0]), "r"(b[1]));
}
__device__ __forceinline__ uint32_t swz(uint32_t off) { return off ^ ((off >> 3) & 0x70); }

// ---------------------------------------------------------------------------
// Kernel 1: circle-blend weights -> fp16, K-major [m][c]
// ---------------------------------------------------------------------------
__global__ void blend_weights_kernel(const float* __restrict__ weight) {
    int t = blockIdx.x * blockDim.x + threadIdx.x;
    if (t >= COUT * CIN) return;
    int o = t >> 8;
    int c = t & 255;
    const float* wp = weight + ((size_t)(o * CIN + c)) * K2;
    float w0 = wp[0], w1 = wp[1], w2 = wp[2];
    float w3 = wp[3], w4 = wp[4], w5 = wp[5];
    float w6 = wp[6], w7 = wp[7], w8 = wp[8];

    const float A  = 0.7071067811865476f;
    const float Bc = 1.0f - 0.7071067811865476f;

    float t01 = A * w0 + Bc * w1;
    float t34 = A * w3 + Bc * w4;
    float t12 = Bc * w1 + A * w2;
    float t45 = Bc * w4 + A * w5;
    float t67 = A * w6 + Bc * w7;
    float t78 = Bc * w7 + A * w8;

    float nw[K2];
    nw[0] = A * t01 + Bc * t34;  nw[1] = w1;
    nw[2] = A * t12 + Bc * t45;  nw[3] = w3;  nw[4] = w4;  nw[5] = w5;
    nw[6] = Bc * t34 + A * t67;  nw[7] = w7;
    nw[8] = Bc * t45 + A * t78;

#pragma unroll
    for (int k = 0; k < K2; k++)
        g_Wh[(size_t)(k * COUT + o) * K_GEMM + c] = __float2half_rn(nw[k]);
}

// ---------------------------------------------------------------------------
// Kernel 2: transpose x[b][c][n] -> Xt[b][n][c] in fp16
// ---------------------------------------------------------------------------
__global__ __launch_bounds__(256) void transpose_split_kernel(const float* __restrict__ X) {
    __shared__ float t[32][33];
    int b  = blockIdx.z;
    int n0 = blockIdx.x * 32;
    int c0 = blockIdx.y * 32;
    int tx = threadIdx.x, ty = threadIdx.y;

    const float* src = X + ((size_t)b * CIN + c0) * HW + n0;
#pragma unroll
    for (int i = ty; i < 32; i += 8)
        t[i][tx] = src[(size_t)i * HW + tx];
    __syncthreads();

    __half* dh = g_Xh + ((size_t)b * HW + n0) * CIN + c0;
#pragma unroll
    for (int i = ty; i < 32; i += 8)
        dh[(size_t)i * CIN + tx] = __float2half_rn(t[tx][i]);
}

// ---------------------------------------------------------------------------
// Kernel 3: fp16 single-pass GEMM (A = Xt rows n, B = W rows m)
//   G[b][k][n][o] = sum_c Xh[b][n][c] * Wh[k*256+o][c]
// ---------------------------------------------------------------------------
extern __shared__ __align__(1024) unsigned char dsmem[];

__global__ __launch_bounds__(256, 2) void gemm_fp16_kernel() {
    const int tid  = threadIdx.x;
    const int wid  = tid >> 5;
    const int lane = tid & 31;
    const int warp_m = wid >> 2;       // 0..1  (64 n-rows each)
    const int warp_n = wid & 3;        // 0..3  (32 m-cols each)

    const int b  = blockIdx.z;
    const int n0 = blockIdx.x * BM;    // n tile (A rows)
    const int m0 = blockIdx.y * BN;    // m tile (B rows)

    const uint32_t sbase = smem_u32(dsmem);

    const __half* A_g = g_Xh + ((size_t)b * HW + n0) * CIN;
    const __half* B_g = g_Wh + (size_t)m0 * K_GEMM;

    auto copy_chunk = [&](int ch) {
        const uint32_t sb = sbase + (ch & 1) * STAGE_B;
        const int k0 = ch * BK;
#pragma unroll
        for (int t = 0; t < 4; t++) {
            int u = t * 256 + tid;          // 0..1023
            int r = u >> 3;                 // row 0..127
            int q = u & 7;                  // 16B unit in row
            uint32_t doff = swz((uint32_t)(r * 128 + q * 16));
            CP16(sb + doff,          A_g + (size_t)r * CIN    + k0 + q * 8);
            CP16(sb + TILE_B + doff, B_g + (size_t)r * K_GEMM + k0 + q * 8);
        }
        CP_COMMIT();
    };

    float acc[4][4][4] = {};   // [mf][jj][reg]

    const int arow = warp_m * 64 + (lane & 15);
    const int acol = (lane & 16);
    const int nloc = ((lane >> 4) & 1) * 8 + (lane & 7);
    const int bcol = ((lane >> 3) & 1) * 16;

    copy_chunk(0);
    copy_chunk(1);

    for (int ch = 0; ch < NCHUNK; ch++) {
        if (ch < NCHUNK - 1) { CP_WAIT(1); } else { CP_WAIT(0); }
        __syncthreads();

        const uint32_t sb = sbase + (ch & 1) * STAGE_B;
        const uint32_t tA = sb;
        const uint32_t tB = sb + TILE_B;

#pragma unroll
        for (int kf = 0; kf < BK / 16; kf++) {
            uint32_t af[4][4];
#pragma unroll
            for (int mf = 0; mf < 4; mf++) {
                uint32_t off = swz((uint32_t)((arow + mf * 16) * 128 + kf * 32 + acol));
                ldsm_x4(af[mf], tA + off);
            }
            uint32_t bf[4][2];
#pragma unroll
            for (int jp = 0; jp < 2; jp++) {
                uint32_t off = swz((uint32_t)((warp_n * 32 + jp * 16 + nloc) * 128 + kf * 32 + bcol));
                uint32_t rh[4];
                ldsm_x4(rh, tB + off);
                bf[2*jp][0]   = rh[0]; bf[2*jp][1]   = rh[1];
                bf[2*jp+1][0] = rh[2]; bf[2*jp+1][1] = rh[3];
            }
#pragma unroll
            for (int mf = 0; mf < 4; mf++)
#pragma unroll
                for (int jj = 0; jj < 4; jj++)
                    mma_fp16(acc[mf][jj], af[mf], bf[jj]);
        }

        if (ch + 2 < NCHUNK) {
            __syncthreads();
            copy_chunk(ch + 2);
        }
    }

    // ---- epilogue: rows = n, cols = o (m within fixed tap k) ----
    const int k_blk = m0 >> 8;          // tap index
    const int o0    = m0 & 255;         // o base (0 or 128)
    float* Gout = g_G + ((size_t)(b * K2 + k_blk)) * HW * COUT;

    const int rbase = n0 + warp_m * 64 + (lane >> 2);          // n
    const int cbase = o0 + warp_n * 32 + (lane & 3) * 2;       // o
#pragma unroll
    for (int mf = 0; mf < 4; mf++) {
#pragma unroll
        for (int jj = 0; jj < 4; jj++) {
            int n = rbase + mf * 16;
            int o = cbase + jj * 8;
            *reinterpret_cast<float2*>(&Gout[(size_t)n * COUT + o]) =
                make_float2(acc[mf][jj][0], acc[mf][jj][1]);
            *reinterpret_cast<float2*>(&Gout[(size_t)(n + 8) * COUT + o]) =
                make_float2(acc[mf][jj][2], acc[mf][jj][3]);
        }
    }
}

// ---------------------------------------------------------------------------
// Kernel 4: combine — coalesced bilinear gather over G[b][k][n][o]
// ---------------------------------------------------------------------------
#define PPB 8
__global__ __launch_bounds__(256) void combine_kernel(
    const float* __restrict__ offset,
    const float* __restrict__ mask,
    const float* __restrict__ bias,
    float* __restrict__ out)
{
    __shared__ int4   s_idx[PPB][K2];
    __shared__ float4 s_cw[PPB][K2];
    __shared__ float  s_out[PPB][COUT];

    const int b    = blockIdx.y;
    const int p0   = blockIdx.x * PPB;
    const int tid  = threadIdx.x;
    const int w    = tid >> 5;
    const int lane = tid & 31;
    const int p    = p0 + w;

    if (lane < K2) {
        const int k  = lane;
        const int py = p >> 6;
        const int px = p & 63;

        float dy = offset[((b * 2 * K2) + 2 * k    ) * HW + p];
        float dx = offset[((b * 2 * K2) + 2 * k + 1) * HW + p];
        float m  = mask[(b * K2 + k) * HW + p];

        float yy = (float)(py - 1 + (k / 3)) + dy;
        float xx = (float)(px - 1 + (k % 3)) + dx;

        float y0f = floorf(yy), x0f = floorf(xx);
        float ly = yy - y0f, lx = xx - x0f;
        float hy = 1.0f - ly, hx = 1.0f - lx;
        int y0 = (int)y0f, x0 = (int)x0f;
        int y1 = y0 + 1,   x1 = x0 + 1;

        bool vy0 = (y0 >= 0) && (y0 < HDIM);
        bool vy1 = (y1 >= 0) && (y1 < HDIM);
        bool vx0 = (x0 >= 0) && (x0 < WDIM);
        bool vx1 = (x1 >= 0) && (x1 < WDIM);

        int cy0 = min(max(y0, 0), HDIM - 1);
        int cy1 = min(max(y1, 0), HDIM - 1);
        int cx0 = min(max(x0, 0), WDIM - 1);
        int cx1 = min(max(x1, 0), WDIM - 1);

        s_idx[w][k] = make_int4(cy0 * WDIM + cx0, cy0 * WDIM + cx1,
                                cy1 * WDIM + cx0, cy1 * WDIM + cx1);
        s_cw[w][k]  = make_float4((vy0 && vx0) ? hy * hx * m : 0.0f,
                                  (vy0 && vx1) ? hy * lx * m : 0.0f,
                                  (vy1 && vx0) ? ly * hx * m : 0.0f,
                                  (vy1 && vx1) ? ly * lx * m : 0.0f);
    }
    __syncwarp();

    const int o8 = lane * 8;
    float acc[8];
    {
        const float4* b4 = reinterpret_cast<const float4*>(bias + o8);
        float4 b0 = b4[0], b1 = b4[1];
        acc[0] = b0.x; acc[1] = b0.y; acc[2] = b0.z; acc[3] = b0.w;
        acc[4] = b1.x; acc[5] = b1.y; acc[6] = b1.z; acc[7] = b1.w;
    }

#pragma unroll
    for (int k = 0; k < K2; k++) {
        int4   id = s_idx[w][k];
        float4 cw = s_cw[w][k];
        const float* base = g_G + ((size_t)(b * K2 + k)) * HW * COUT + o8;

        const float4* q0 = reinterpret_cast<const float4*>(base + (size_t)id.x * COUT);
        const float4* q1 = reinterpret_cast<const float4*>(base + (size_t)id.y * COUT);
        const float4* q2 = reinterpret_cast<const float4*>(base + (size_t)id.z * COUT);
        const float4* q3 = reinterpret_cast<const float4*>(base + (size_t)id.w * COUT);
        float4 a0 = q0[0], a1 = q0[1];
        float4 b0 = q1[0], b1 = q1[1];
        float4 c0 = q2[0], c1 = q2[1];
        float4 d0 = q3[0], d1 = q3[1];

        acc[0] += cw.x * a0.x + cw.y * b0.x + cw.z * c0.x + cw.w * d0.x;
        acc[1] += cw.x * a0.y + cw.y * b0.y + cw.z * c0.y + cw.w * d0.y;
        acc[2] += cw.x * a0.z + cw.y * b0.z + cw.z * c0.z + cw.w * d0.z;
        acc[3] += cw.x * a0.w + cw.y * b0.w + cw.z * c0.w + cw.w * d0.w;
        acc[4] += cw.x * a1.x + cw.y * b1.x + cw.z * c1.x + cw.w * d1.x;
        acc[5] += cw.x * a1.y + cw.y * b1.y + cw.z * c1.y + cw.w * d1.y;
        acc[6] += cw.x * a1.z + cw.y * b1.z + cw.z * c1.z + cw.w * d1.z;
        acc[7] += cw.x * a1.w + cw.y * b1.w + cw.z * c1.w + cw.w * d1.w;
    }

#pragma unroll
    for (int j = 0; j < 8; j++) s_out[w][o8 + j] = acc[j];
    __syncthreads();

    {
        const int o = tid;
        float4 r0 = make_float4(s_out[0][o], s_out[1][o], s_out[2][o], s_out[3][o]);
        float4 r1 = make_float4(s_out[4][o], s_out[5][o], s_out[6][o], s_out[7][o]);
        float* dst = out + ((size_t)(b * COUT + o)) * HW + p0;
        *reinterpret_cast<float4*>(dst)     = r0;
        *reinterpret_cast<float4*>(dst + 4) = r1;
    }
}

// ---------------------------------------------------------------------------
extern "C" void kernel_launch(void* const* d_in, const int* in_sizes, int n_in,
                              void* d_out, int out_size) {
    const float* x      = (const float*)d_in[0];   // [4,256,64,64]
    const float* offset = (const float*)d_in[1];   // [4,18,64,64]
    const float* mask   = (const float*)d_in[2];   // [4,9,64,64]
    const float* weight = (const float*)d_in[3];   // [256,256,3,3]
    const float* bias   = (const float*)d_in[4];   // [256]
    float* out = (float*)d_out;                    // [4,256,64,64]

    static bool attr_set = false;
    if (!attr_set) {
        cudaFuncSetAttribute(gemm_fp16_kernel,
                             cudaFuncAttributeMaxDynamicSharedMemorySize, SMEM_DYN);
        attr_set = true;
    }

    blend_weights_kernel<<<(COUT * CIN + 255) / 256, 256>>>(weight);
    transpose_split_kernel<<<dim3(HW / 32, CIN / 32, BATCH), dim3(32, 8)>>>(x);
    gemm_fp16_kernel<<<dim3(HW / BM, M_GEMM / BN, BATCH), 256, SMEM_DYN>>>();
    combine_kernel<<<dim3(HW / PPB, BATCH), 256>>>(offset, mask, bias, out);
}

// round 7
// speedup vs baseline: 6.2815x; 1.1882x over previous
#include <cuda_runtime.h>
#include <cuda_fp16.h>
#include <cstdint>

// ---------------- problem constants ----------------
#define CIN    256
#define COUT   256
#define HDIM   64
#define WDIM   64
#define BATCH  4
#define K2     9
#define HW     4096
#define M_GEMM 2304          // K2 * COUT
#define K_GEMM 256           // CIN

// ---------------- GEMM tiling ----------------
#define BM 128                         // n-tile rows
#define BN 128                         // m-tile cols
#define BK 64                          // fp16 elements per chunk (128B rows)
#define NCHUNK (K_GEMM / BK)           // 4
#define TILE_B (BM * BK * 2)           // 16384 bytes per operand tile
#define STAGE_B (2 * TILE_B)           // A, B = 32 KB
#define SMEM_DYN (2 * STAGE_B)         // 64 KB

// ---------------- scratch (device globals) ----------------
__device__ __half g_Wh[M_GEMM * K_GEMM];      // [m][c]
__device__ __half g_Xh[BATCH * HW * CIN];     // [b][n][c]
// layout: G[b][k][n][o]  (o contiguous), fp16.  75.5 MB
__device__ __half g_Gh[(size_t)BATCH * K2 * HW * COUT];

// ---------------- PTX helpers ----------------
__device__ __forceinline__ uint32_t smem_u32(const void* p) {
    uint32_t a;
    asm("{ .reg .u64 t; cvta.to.shared.u64 t, %1; cvt.u32.u64 %0, t; }" : "=r"(a) : "l"(p));
    return a;
}
#define CP16(dst, src)  asm volatile("cp.async.cg.shared.global [%0], [%1], 16;" :: "r"(dst), "l"(src) : "memory")
#define CP_COMMIT()     asm volatile("cp.async.commit_group;" ::: "memory")
#define CP_WAIT(n)      asm volatile("cp.async.wait_group %0;" :: "n"(n) : "memory")

__device__ __forceinline__ void ldsm_x4(uint32_t* r, uint32_t addr) {
    asm volatile("ldmatrix.sync.aligned.m8n8.x4.shared.b16 {%0,%1,%2,%3}, [%4];"
                 : "=r"(r[0]), "=r"(r[1]), "=r"(r[2]), "=r"(r[3]) : "r"(addr));
}
__device__ __forceinline__ void mma_fp16(float* d, const uint32_t* a, const uint32_t* b) {
    asm volatile("mma.sync.aligned.m16n8k16.row.col.f32.f16.f16.f32 "
                 "{%0,%1,%2,%3}, {%4,%5,%6,%7}, {%8,%9}, {%0,%1,%2,%3};"
                 : "+f"(d[0]), "+f"(d[1]), "+f"(d[2]), "+f"(d[3])
                 : "r"(a[0]), "r"(a[1]), "r"(a[2]), "r"(a[3]), "r"(b[0]), "r"(b[1]));
}
__device__ __forceinline__ uint32_t swz(uint32_t off) { return off ^ ((off >> 3) & 0x70); }

// ---------------------------------------------------------------------------
// Kernel 1: circle-blend weights -> fp16, K-major [m][c]
// ---------------------------------------------------------------------------
__global__ void blend_weights_kernel(const float* __restrict__ weight) {
    int t = blockIdx.x * blockDim.x + threadIdx.x;
    if (t >= COUT * CIN) return;
    int o = t >> 8;
    int c = t & 255;
    const float* wp = weight + ((size_t)(o * CIN + c)) * K2;
    float w0 = wp[0], w1 = wp[1], w2 = wp[2];
    float w3 = wp[3], w4 = wp[4], w5 = wp[5];
    float w6 = wp[6], w7 = wp[7], w8 = wp[8];

    const float A  = 0.7071067811865476f;
    const float Bc = 1.0f - 0.7071067811865476f;

    float t01 = A * w0 + Bc * w1;
    float t34 = A * w3 + Bc * w4;
    float t12 = Bc * w1 + A * w2;
    float t45 = Bc * w4 + A * w5;
    float t67 = A * w6 + Bc * w7;
    float t78 = Bc * w7 + A * w8;

    float nw[K2];
    nw[0] = A * t01 + Bc * t34;  nw[1] = w1;
    nw[2] = A * t12 + Bc * t45;  nw[3] = w3;  nw[4] = w4;  nw[5] = w5;
    nw[6] = Bc * t34 + A * t67;  nw[7] = w7;
    nw[8] = Bc * t45 + A * t78;

#pragma unroll
    for (int k = 0; k < K2; k++)
        g_Wh[(size_t)(k * COUT + o) * K_GEMM + c] = __float2half_rn(nw[k]);
}

// ---------------------------------------------------------------------------
// Kernel 2: transpose x[b][c][n] -> Xt[b][n][c] in fp16
// ---------------------------------------------------------------------------
__global__ __launch_bounds__(256) void transpose_split_kernel(const float* __restrict__ X) {
    __shared__ float t[32][33];
    int b  = blockIdx.z;
    int n0 = blockIdx.x * 32;
    int c0 = blockIdx.y * 32;
    int tx = threadIdx.x, ty = threadIdx.y;

    const float* src = X + ((size_t)b * CIN + c0) * HW + n0;
#pragma unroll
    for (int i = ty; i < 32; i += 8)
        t[i][tx] = src[(size_t)i * HW + tx];
    __syncthreads();

    __half* dh = g_Xh + ((size_t)b * HW + n0) * CIN + c0;
#pragma unroll
    for (int i = ty; i < 32; i += 8)
        dh[(size_t)i * CIN + tx] = __float2half_rn(t[tx][i]);
}

// ---------------------------------------------------------------------------
// Kernel 3: fp16 single-pass GEMM (A = Xt rows n, B = W rows m)
//   G[b][k][n][o] = sum_c Xh[b][n][c] * Wh[k*256+o][c]   (stored fp16)
// ---------------------------------------------------------------------------
extern __shared__ __align__(1024) unsigned char dsmem[];

__global__ __launch_bounds__(256, 2) void gemm_fp16_kernel() {
    const int tid  = threadIdx.x;
    const int wid  = tid >> 5;
    const int lane = tid & 31;
    const int warp_m = wid >> 2;       // 0..1  (64 n-rows each)
    const int warp_n = wid & 3;        // 0..3  (32 m-cols each)

    const int b  = blockIdx.z;
    const int n0 = blockIdx.x * BM;    // n tile (A rows)
    const int m0 = blockIdx.y * BN;    // m tile (B rows)

    const uint32_t sbase = smem_u32(dsmem);

    const __half* A_g = g_Xh + ((size_t)b * HW + n0) * CIN;
    const __half* B_g = g_Wh + (size_t)m0 * K_GEMM;

    auto copy_chunk = [&](int ch) {
        const uint32_t sb = sbase + (ch & 1) * STAGE_B;
        const int k0 = ch * BK;
#pragma unroll
        for (int t = 0; t < 4; t++) {
            int u = t * 256 + tid;          // 0..1023
            int r = u >> 3;                 // row 0..127
            int q = u & 7;                  // 16B unit in row
            uint32_t doff = swz((uint32_t)(r * 128 + q * 16));
            CP16(sb + doff,          A_g + (size_t)r * CIN    + k0 + q * 8);
            CP16(sb + TILE_B + doff, B_g + (size_t)r * K_GEMM + k0 + q * 8);
        }
        CP_COMMIT();
    };

    float acc[4][4][4] = {};   // [mf][jj][reg]

    const int arow = warp_m * 64 + (lane & 15);
    const int acol = (lane & 16);
    const int nloc = ((lane >> 4) & 1) * 8 + (lane & 7);
    const int bcol = ((lane >> 3) & 1) * 16;

    copy_chunk(0);
    copy_chunk(1);

    for (int ch = 0; ch < NCHUNK; ch++) {
        if (ch < NCHUNK - 1) { CP_WAIT(1); } else { CP_WAIT(0); }
        __syncthreads();

        const uint32_t sb = sbase + (ch & 1) * STAGE_B;
        const uint32_t tA = sb;
        const uint32_t tB = sb + TILE_B;

#pragma unroll
        for (int kf = 0; kf < BK / 16; kf++) {
            uint32_t af[4][4];
#pragma unroll
            for (int mf = 0; mf < 4; mf++) {
                uint32_t off = swz((uint32_t)((arow + mf * 16) * 128 + kf * 32 + acol));
                ldsm_x4(af[mf], tA + off);
            }
            uint32_t bf[4][2];
#pragma unroll
            for (int jp = 0; jp < 2; jp++) {
                uint32_t off = swz((uint32_t)((warp_n * 32 + jp * 16 + nloc) * 128 + kf * 32 + bcol));
                uint32_t rh[4];
                ldsm_x4(rh, tB + off);
                bf[2*jp][0]   = rh[0]; bf[2*jp][1]   = rh[1];
                bf[2*jp+1][0] = rh[2]; bf[2*jp+1][1] = rh[3];
            }
#pragma unroll
            for (int mf = 0; mf < 4; mf++)
#pragma unroll
                for (int jj = 0; jj < 4; jj++)
                    mma_fp16(acc[mf][jj], af[mf], bf[jj]);
        }

        if (ch + 2 < NCHUNK) {
            __syncthreads();
            copy_chunk(ch + 2);
        }
    }

    // ---- epilogue: rows = n, cols = o (m within fixed tap k), fp16 stores ----
    const int k_blk = m0 >> 8;          // tap index
    const int o0    = m0 & 255;         // o base (0 or 128)
    __half* Gout = g_Gh + ((size_t)(b * K2 + k_blk)) * HW * COUT;

    const int rbase = n0 + warp_m * 64 + (lane >> 2);          // n
    const int cbase = o0 + warp_n * 32 + (lane & 3) * 2;       // o
#pragma unroll
    for (int mf = 0; mf < 4; mf++) {
#pragma unroll
        for (int jj = 0; jj < 4; jj++) {
            int n = rbase + mf * 16;
            int o = cbase + jj * 8;
            *reinterpret_cast<__half2*>(&Gout[(size_t)n * COUT + o]) =
                __floats2half2_rn(acc[mf][jj][0], acc[mf][jj][1]);
            *reinterpret_cast<__half2*>(&Gout[(size_t)(n + 8) * COUT + o]) =
                __floats2half2_rn(acc[mf][jj][2], acc[mf][jj][3]);
        }
    }
}

// ---------------------------------------------------------------------------
// Kernel 4: combine — coalesced bilinear gather over fp16 G[b][k][n][o]
//   1 warp per pixel, 8 pixels per CTA; lane owns 8 o-channels (16B per corner).
// ---------------------------------------------------------------------------
#define PPB 8
__global__ __launch_bounds__(256) void combine_kernel(
    const float* __restrict__ offset,
    const float* __restrict__ mask,
    const float* __restrict__ bias,
    float* __restrict__ out)
{
    __shared__ int4   s_idx[PPB][K2];
    __shared__ float4 s_cw[PPB][K2];
    __shared__ float  s_out[PPB][COUT];

    const int b    = blockIdx.y;
    const int p0   = blockIdx.x * PPB;
    const int tid  = threadIdx.x;
    const int w    = tid >> 5;
    const int lane = tid & 31;
    const int p    = p0 + w;

    if (lane < K2) {
        const int k  = lane;
        const int py = p >> 6;
        const int px = p & 63;

        float dy = offset[((b * 2 * K2) + 2 * k    ) * HW + p];
        float dx = offset[((b * 2 * K2) + 2 * k + 1) * HW + p];
        float m  = mask[(b * K2 + k) * HW + p];

        float yy = (float)(py - 1 + (k / 3)) + dy;
        float xx = (float)(px - 1 + (k % 3)) + dx;

        float y0f = floorf(yy), x0f = floorf(xx);
        float ly = yy - y0f, lx = xx - x0f;
        float hy = 1.0f - ly, hx = 1.0f - lx;
        int y0 = (int)y0f, x0 = (int)x0f;
        int y1 = y0 + 1,   x1 = x0 + 1;

        bool vy0 = (y0 >= 0) && (y0 < HDIM);
        bool vy1 = (y1 >= 0) && (y1 < HDIM);
        bool vx0 = (x0 >= 0) && (x0 < WDIM);
        bool vx1 = (x1 >= 0) && (x1 < WDIM);

        int cy0 = min(max(y0, 0), HDIM - 1);
        int cy1 = min(max(y1, 0), HDIM - 1);
        int cx0 = min(max(x0, 0), WDIM - 1);
        int cx1 = min(max(x1, 0), WDIM - 1);

        s_idx[w][k] = make_int4(cy0 * WDIM + cx0, cy0 * WDIM + cx1,
                                cy1 * WDIM + cx0, cy1 * WDIM + cx1);
        s_cw[w][k]  = make_float4((vy0 && vx0) ? hy * hx * m : 0.0f,
                                  (vy0 && vx1) ? hy * lx * m : 0.0f,
                                  (vy1 && vx0) ? ly * hx * m : 0.0f,
                                  (vy1 && vx1) ? ly * lx * m : 0.0f);
    }
    __syncwarp();

    const int o8 = lane * 8;
    float acc[8];
    {
        const float4* b4 = reinterpret_cast<const float4*>(bias + o8);
        float4 b0 = b4[0], b1 = b4[1];
        acc[0] = b0.x; acc[1] = b0.y; acc[2] = b0.z; acc[3] = b0.w;
        acc[4] = b1.x; acc[5] = b1.y; acc[6] = b1.z; acc[7] = b1.w;
    }

#pragma unroll
    for (int k = 0; k < K2; k++) {
        int4   id = s_idx[w][k];
        float4 cw = s_cw[w][k];
        const __half* base = g_Gh + ((size_t)(b * K2 + k)) * HW * COUT + o8;

        uint4 v0 = *reinterpret_cast<const uint4*>(base + (size_t)id.x * COUT);
        uint4 v1 = *reinterpret_cast<const uint4*>(base + (size_t)id.y * COUT);
        uint4 v2 = *reinterpret_cast<const uint4*>(base + (size_t)id.z * COUT);
        uint4 v3 = *reinterpret_cast<const uint4*>(base + (size_t)id.w * COUT);

        const __half2* h0 = reinterpret_cast<const __half2*>(&v0);
        const __half2* h1 = reinterpret_cast<const __half2*>(&v1);
        const __half2* h2 = reinterpret_cast<const __half2*>(&v2);
        const __half2* h3 = reinterpret_cast<const __half2*>(&v3);

#pragma unroll
        for (int j = 0; j < 4; j++) {
            float2 a = __half22float2(h0[j]);
            float2 bb = __half22float2(h1[j]);
            float2 c = __half22float2(h2[j]);
            float2 d = __half22float2(h3[j]);
            acc[2*j]   += cw.x * a.x + cw.y * bb.x + cw.z * c.x + cw.w * d.x;
            acc[2*j+1] += cw.x * a.y + cw.y * bb.y + cw.z * c.y + cw.w * d.y;
        }
    }

#pragma unroll
    for (int j = 0; j < 8; j++) s_out[w][o8 + j] = acc[j];
    __syncthreads();

    {
        const int o = tid;
        float4 r0 = make_float4(s_out[0][o], s_out[1][o], s_out[2][o], s_out[3][o]);
        float4 r1 = make_float4(s_out[4][o], s_out[5][o], s_out[6][o], s_out[7][o]);
        float* dst = out + ((size_t)(b * COUT + o)) * HW + p0;
        *reinterpret_cast<float4*>(dst)     = r0;
        *reinterpret_cast<float4*>(dst + 4) = r1;
    }
}

// ---------------------------------------------------------------------------
extern "C" void kernel_launch(void* const* d_in, const int* in_sizes, int n_in,
                              void* d_out, int out_size) {
    const float* x      = (const float*)d_in[0];   // [4,256,64,64]
    const float* offset = (const float*)d_in[1];   // [4,18,64,64]
    const float* mask   = (const float*)d_in[2];   // [4,9,64,64]
    const float* weight = (const float*)d_in[3];   // [256,256,3,3]
    const float* bias   = (const float*)d_in[4];   // [256]
    float* out = (float*)d_out;                    // [4,256,64,64]

    static bool attr_set = false;
    if (!attr_set) {
        cudaFuncSetAttribute(gemm_fp16_kernel,
                             cudaFuncAttributeMaxDynamicSharedMemorySize, SMEM_DYN);
        attr_set = true;
    }

    blend_weights_kernel<<<(COUT * CIN + 255) / 256, 256>>>(weight);
    transpose_split_kernel<<<dim3(HW / 32, CIN / 32, BATCH), dim3(32, 8)>>>(x);
    gemm_fp16_kernel<<<dim3(HW / BM, M_GEMM / BN, BATCH), 256, SMEM_DYN>>>();
    combine_kernel<<<dim3(HW / PPB, BATCH), 256>>>(offset, mask, bias, out);
}